// round 4
// baseline (speedup 1.0000x reference)
#include <cuda_runtime.h>
#include <cuda_bf16.h>

// Inputs (metadata order):
// 0 node_features (N,64) f32
// 1 edge_index    (2,E)  int32 (JAX x64-disabled: randint int64 downcasts to int32)
// 2 edge_features (E,32) f32
// 3 W1 (96,64)  4 b1(64)  5 g1(64)  6 be1(64)
// 7 W2 (64,64)  8 b2(64)
// 9 Wu (128,64) 10 bu(64) 11 gn(64) 12 bn(64)
// out: (N,64) f32

#define FULL 0xFFFFFFFFu
#define MAX_N 80000

__device__ __align__(16) float g_agg[(size_t)MAX_N * 64];

__device__ __forceinline__ float silu(float v) {
    return v * (1.0f / (1.0f + __expf(-v)));
}

// ---------------------------------------------------------------- zero agg
__global__ void zero_kernel(long long n4) {
    long long i = (long long)blockIdx.x * blockDim.x + threadIdx.x;
    if (i < n4) ((float4*)g_agg)[i] = make_float4(0.f, 0.f, 0.f, 0.f);
}

// ---------------------------------------------------------------- edge MLP + scatter
// One warp processes 4 edges per iteration. Inputs live in registers,
// broadcast via shuffles; only weights live in (static) smem.
__global__ __launch_bounds__(256) void edge_kernel(
    const float* __restrict__ nodef,
    const int* __restrict__ ei,
    const float* __restrict__ edgef,
    const float* __restrict__ W1, const float* __restrict__ b1,
    const float* __restrict__ g1, const float* __restrict__ be1,
    const float* __restrict__ W2, const float* __restrict__ b2,
    long long E)
{
    __shared__ float2 sW1[96 * 32];   // 24 KB : W1 row k -> lane l holds cols 2l,2l+1
    __shared__ float2 sW2[64 * 32];   // 16 KB
    __shared__ float  sb1[64], sg1[64], sbe1[64], sb2[64];

    for (int i = threadIdx.x; i < 96 * 32; i += blockDim.x) {
        int k = i >> 5, l = i & 31;
        sW1[i] = make_float2(W1[k * 64 + 2 * l], W1[k * 64 + 2 * l + 1]);
    }
    for (int i = threadIdx.x; i < 64 * 32; i += blockDim.x) {
        int k = i >> 5, l = i & 31;
        sW2[i] = make_float2(W2[k * 64 + 2 * l], W2[k * 64 + 2 * l + 1]);
    }
    if (threadIdx.x < 64) {
        int t = threadIdx.x;
        sb1[t] = b1[t]; sg1[t] = g1[t]; sbe1[t] = be1[t]; sb2[t] = b2[t];
    }
    __syncthreads();

    const int lane = threadIdx.x & 31;
    const int warp = threadIdx.x >> 5;

    const long long G = (E + 3) >> 2;
    const long long wstride = (long long)gridDim.x * (blockDim.x >> 5);
    const int* srcp = ei;
    const int* tgtp = ei + E;

    const float gx  = sg1[2 * lane],  gy  = sg1[2 * lane + 1];
    const float bx  = sbe1[2 * lane], by  = sbe1[2 * lane + 1];
    const float2 a0 = make_float2(sb1[2 * lane], sb1[2 * lane + 1]);
    const float2 b0 = make_float2(sb2[2 * lane], sb2[2 * lane + 1]);

    for (long long g = (long long)blockIdx.x * (blockDim.x >> 5) + warp; g < G; g += wstride) {
        long long e0 = g << 2;
        int sA = 0, tA = 0;
        if (lane < 4) {
            long long ee = e0 + lane; if (ee >= E) ee = E - 1;
            sA = srcp[ee]; tA = tgtp[ee];
        }

        // Register-resident input block: lane l holds x[e][l], x[e][32+l], x[e][64+l]
        // where x = [node_features[src] (64) | edge_features (32)].
        float xa[4], xb[4], xc[4];
        #pragma unroll
        for (int e = 0; e < 4; e++) {
            long long ee = e0 + e; if (ee >= E) ee = E - 1;
            int s = __shfl_sync(FULL, sA, e);
            const float* np = nodef + (long long)s * 64;
            xa[e] = np[lane];
            xb[e] = np[32 + lane];
            xc[e] = edgef[ee * 32 + lane];
        }

        // GEMM1: (4,96) @ (96,64); lane owns outputs 2*lane, 2*lane+1
        float2 acc[4] = {a0, a0, a0, a0};
        #pragma unroll
        for (int k = 0; k < 96; k++) {
            float2 w = sW1[k * 32 + lane];
            #pragma unroll
            for (int e = 0; e < 4; e++) {
                float x = (k < 32) ? __shfl_sync(FULL, xa[e], k)
                        : (k < 64) ? __shfl_sync(FULL, xb[e], k - 32)
                                   : __shfl_sync(FULL, xc[e], k - 64);
                acc[e].x = fmaf(x, w.x, acc[e].x);
                acc[e].y = fmaf(x, w.y, acc[e].y);
            }
        }

        // LayerNorm over 64 outputs per edge (warp reduction), then SiLU
        float s[4], q[4];
        #pragma unroll
        for (int e = 0; e < 4; e++) {
            s[e] = acc[e].x + acc[e].y;
            q[e] = acc[e].x * acc[e].x + acc[e].y * acc[e].y;
        }
        #pragma unroll
        for (int off = 16; off; off >>= 1) {
            #pragma unroll
            for (int e = 0; e < 4; e++) {
                s[e] += __shfl_xor_sync(FULL, s[e], off);
                q[e] += __shfl_xor_sync(FULL, q[e], off);
            }
        }
        float2 h[4];
        #pragma unroll
        for (int e = 0; e < 4; e++) {
            float mean = s[e] * (1.0f / 64.0f);
            float var  = q[e] * (1.0f / 64.0f) - mean * mean;
            float rstd = rsqrtf(var + 1e-5f);
            h[e].x = silu((acc[e].x - mean) * rstd * gx + bx);
            h[e].y = silu((acc[e].y - mean) * rstd * gy + by);
        }

        // GEMM2: (4,64) @ (64,64); h[e][k] lives on lane k>>1, component k&1
        float2 acc2[4] = {b0, b0, b0, b0};
        #pragma unroll
        for (int k = 0; k < 64; k++) {
            float2 w = sW2[k * 32 + lane];
            #pragma unroll
            for (int e = 0; e < 4; e++) {
                float hv = (k & 1) ? __shfl_sync(FULL, h[e].y, k >> 1)
                                   : __shfl_sync(FULL, h[e].x, k >> 1);
                acc2[e].x = fmaf(hv, w.x, acc2[e].x);
                acc2[e].y = fmaf(hv, w.y, acc2[e].y);
            }
        }

        // SiLU + vectorized scatter-add into g_agg[tgt]
        #pragma unroll
        for (int e = 0; e < 4; e++) {
            float mx = silu(acc2[e].x);
            float my = silu(acc2[e].y);
            int tg = __shfl_sync(FULL, tA, e);
            if (e0 + e < E) {
                float* p = g_agg + (long long)tg * 64 + 2 * lane;
                asm volatile("red.global.add.v2.f32 [%0], {%1, %2};"
                             :: "l"(p), "f"(mx), "f"(my) : "memory");
            }
        }
    }
}

// ---------------------------------------------------------------- node update
__global__ __launch_bounds__(256) void node_kernel(
    const float* __restrict__ nodef,
    const float* __restrict__ Wu, const float* __restrict__ bu,
    const float* __restrict__ gn, const float* __restrict__ bn,
    float* __restrict__ out, long long N)
{
    __shared__ float2 sWu[128 * 32];   // 32 KB
    __shared__ float  sbu[64], sgn[64], sbn[64];

    for (int i = threadIdx.x; i < 128 * 32; i += blockDim.x) {
        int k = i >> 5, l = i & 31;
        sWu[i] = make_float2(Wu[k * 64 + 2 * l], Wu[k * 64 + 2 * l + 1]);
    }
    if (threadIdx.x < 64) {
        int t = threadIdx.x;
        sbu[t] = bu[t]; sgn[t] = gn[t]; sbn[t] = bn[t];
    }
    __syncthreads();

    const int lane = threadIdx.x & 31;
    const int warp = threadIdx.x >> 5;

    const float2 a0 = make_float2(sbu[2 * lane], sbu[2 * lane + 1]);
    const float gx = sgn[2 * lane], gy = sgn[2 * lane + 1];
    const float bx = sbn[2 * lane], by = sbn[2 * lane + 1];

    for (long long n = (long long)blockIdx.x * 8 + warp; n < N; n += (long long)gridDim.x * 8) {
        // combined = [agg (64) | node_features (64)]; lane holds 4 regs
        float ca = g_agg[n * 64 + lane];
        float cb = g_agg[n * 64 + 32 + lane];
        float cc = nodef[n * 64 + lane];
        float cd = nodef[n * 64 + 32 + lane];

        float2 a = a0;
        #pragma unroll
        for (int k = 0; k < 128; k++) {
            float x = (k < 32) ? __shfl_sync(FULL, ca, k)
                    : (k < 64) ? __shfl_sync(FULL, cb, k - 32)
                    : (k < 96) ? __shfl_sync(FULL, cc, k - 64)
                               : __shfl_sync(FULL, cd, k - 96);
            float2 w = sWu[k * 32 + lane];
            a.x = fmaf(x, w.x, a.x);
            a.y = fmaf(x, w.y, a.y);
        }
        a.x = silu(a.x);
        a.y = silu(a.y);

        float s = a.x + a.y;
        float q = a.x * a.x + a.y * a.y;
        #pragma unroll
        for (int off = 16; off; off >>= 1) {
            s += __shfl_xor_sync(FULL, s, off);
            q += __shfl_xor_sync(FULL, q, off);
        }
        float mean = s * (1.0f / 64.0f);
        float var  = q * (1.0f / 64.0f) - mean * mean;
        float rstd = rsqrtf(var + 1e-5f);
        float ox = (a.x - mean) * rstd * gx + bx;
        float oy = (a.y - mean) * rstd * gy + by;
        ((float2*)(out + n * 64))[lane] = make_float2(ox, oy);
    }
}

// ----------------------------------------------------------------
extern "C" void kernel_launch(void* const* d_in, const int* in_sizes, int n_in,
                              void* d_out, int out_size)
{
    const float* nodef = (const float*)d_in[0];
    const int*   ei    = (const int*)d_in[1];
    const float* edgef = (const float*)d_in[2];
    const float* W1    = (const float*)d_in[3];
    const float* b1    = (const float*)d_in[4];
    const float* g1    = (const float*)d_in[5];
    const float* be1   = (const float*)d_in[6];
    const float* W2    = (const float*)d_in[7];
    const float* b2    = (const float*)d_in[8];
    const float* Wu    = (const float*)d_in[9];
    const float* bu    = (const float*)d_in[10];
    const float* gn    = (const float*)d_in[11];
    const float* bn    = (const float*)d_in[12];

    long long N = (long long)in_sizes[0] / 64;
    long long E = (long long)in_sizes[1] / 2;
    float* out = (float*)d_out;

    // 1) zero the aggregation scratch
    long long n4 = N * 16;
    int zblocks = (int)((n4 + 255) / 256);
    zero_kernel<<<zblocks, 256>>>(n4);

    // 2) edge MLP + scatter (static smem only — no attribute opt-in needed)
    edge_kernel<<<592, 256>>>(nodef, ei, edgef, W1, b1, g1, be1, W2, b2, E);

    // 3) node update + final LayerNorm
    node_kernel<<<592, 256>>>(nodef, Wu, bu, gn, bn, out, N);
}

// round 7
// speedup vs baseline: 1.9007x; 1.9007x over previous
#include <cuda_runtime.h>
#include <cstdint>

// Inputs (metadata order):
// 0 node_features (N,64) f32
// 1 edge_index    (2,E)  int32
// 2 edge_features (E,32) f32
// 3 W1 (96,64)  4 b1(64)  5 g1(64)  6 be1(64)
// 7 W2 (64,64)  8 b2(64)
// 9 Wu (128,64) 10 bu(64) 11 gn(64) 12 bn(64)
// out: (N,64) f32

#define FULL 0xFFFFFFFFu
#define MAX_N 80000

__device__ __align__(16) float g_agg[(size_t)MAX_N * 64];

// exact-ish silu for node kernel
__device__ __forceinline__ float silu_exact(float v) {
    return v * (1.0f / (1.0f + __expf(-v)));
}
// fast silu for edge epilogues: v * 0.5*(1+tanh(v/2)) — 1 MUFU
__device__ __forceinline__ float silu_fast(float v) {
    float t;
    asm("tanh.approx.f32 %0, %1;" : "=f"(t) : "f"(v * 0.5f));
    float hv = 0.5f * v;
    return fmaf(hv, t, hv);
}
__device__ __forceinline__ uint32_t f2tf32(float f) {
    uint32_t r;
    asm("cvt.rna.tf32.f32 %0, %1;" : "=r"(r) : "f"(f));
    return r;
}
__device__ __forceinline__ void mma16n8k8(float c[4], uint32_t a0, uint32_t a1,
                                          uint32_t a2, uint32_t a3,
                                          uint32_t b0, uint32_t b1) {
    asm volatile(
        "mma.sync.aligned.m16n8k8.row.col.f32.tf32.tf32.f32 "
        "{%0,%1,%2,%3}, {%4,%5,%6,%7}, {%8,%9}, {%0,%1,%2,%3};"
        : "+f"(c[0]), "+f"(c[1]), "+f"(c[2]), "+f"(c[3])
        : "r"(a0), "r"(a1), "r"(a2), "r"(a3), "r"(b0), "r"(b1));
}

// ---------------------------------------------------------------- zero agg
__global__ void zero_kernel(long long n4) {
    long long i = (long long)blockIdx.x * blockDim.x + threadIdx.x;
    if (i < n4) ((float4*)g_agg)[i] = make_float4(0.f, 0.f, 0.f, 0.f);
}

// ---------------------------------------------------------------- edge MLP (mma.sync tf32) + scatter
// dynamic smem layout (floats):
//   B1f  : 12*8*32 float2   (W1^T in B-fragment order)   24576 B
//   B2f  :  8*8*32 float2                                16384 B
//   pb1|pg|pbe|pb2 : 4*64 f32                             1024 B
//   xin  : 8 warps * 16 rows * 100 f32                   51200 B
// total 93184 B -> 2 CTAs/SM
#define XSTR 100
#define EDGE_SMEM 93184

__global__ __launch_bounds__(256, 2) void edge_kernel(
    const float* __restrict__ nodef,
    const int* __restrict__ ei,
    const float* __restrict__ edgef,
    const float* __restrict__ W1, const float* __restrict__ b1,
    const float* __restrict__ g1, const float* __restrict__ be1,
    const float* __restrict__ W2, const float* __restrict__ b2,
    long long E)
{
    extern __shared__ __align__(16) float smem[];
    float2* B1f = (float2*)smem;            // [12*8*32]
    float2* B2f = B1f + 12 * 8 * 32;        // [8*8*32]
    float*  pb1 = (float*)(B2f + 8 * 8 * 32);
    float*  pg  = pb1 + 64;
    float*  pbe = pg + 64;
    float*  pb2 = pbe + 64;
    float*  xall = pb2 + 64;

    const int t = threadIdx.x;
    const int warp = t >> 5;
    const int lane = t & 31;

    // pack W1^T, W2^T into B-fragment order (tf32-converted)
    for (int i = t; i < 12 * 8 * 32; i += 256) {
        int kt = i >> 8, nt = (i >> 5) & 7, l = i & 31;
        int k = kt * 8 + (l & 3), n = nt * 8 + (l >> 2);
        float2 v;
        v.x = __uint_as_float(f2tf32(W1[k * 64 + n]));
        v.y = __uint_as_float(f2tf32(W1[(k + 4) * 64 + n]));
        B1f[i] = v;
    }
    for (int i = t; i < 8 * 8 * 32; i += 256) {
        int kt = i >> 8, nt = (i >> 5) & 7, l = i & 31;
        int k = kt * 8 + (l & 3), n = nt * 8 + (l >> 2);
        float2 v;
        v.x = __uint_as_float(f2tf32(W2[k * 64 + n]));
        v.y = __uint_as_float(f2tf32(W2[(k + 4) * 64 + n]));
        B2f[i] = v;
    }
    if (t < 64) { pb1[t] = b1[t]; pg[t] = g1[t]; pbe[t] = be1[t]; pb2[t] = b2[t]; }
    __syncthreads();

    float* xin = xall + warp * (16 * XSTR);
    const int j = lane & 3;          // position in 4-lane group
    const int r0 = lane >> 2;        // fragment row (and r0+8)
    const int rr = lane >> 1, hf = lane & 1;   // scatter mapping

    const float4* nf4 = (const float4*)nodef;
    const float4* ef4 = (const float4*)edgef;
    const int* srcp = ei;
    const int* tgtp = ei + E;

    const long long G = (E + 15) >> 4;
    const long long wstride = (long long)gridDim.x * 8;

    for (long long g = (long long)blockIdx.x * 8 + warp; g < G; g += wstride) {
        const long long e0 = g << 4;
        int sA = 0, tA = 0;
        if (lane < 16) {
            long long ee = e0 + lane; if (ee >= E) ee = E - 1;
            sA = srcp[ee]; tA = tgtp[ee];
        }

        // ---- gather 16 edges x 96 floats -> xin (tf32), coalesced float4
        #pragma unroll
        for (int i = 0; i < 12; i++) {
            int idx = lane + 32 * i;            // 0..383
            int e = idx / 24, c = idx - e * 24; // e<16, c<24
            float4 v;
            if (c < 16) {
                int s = __shfl_sync(FULL, sA, e);
                v = nf4[(long long)s * 16 + c];
            } else {
                long long ee = e0 + e; if (ee >= E) ee = E - 1;
                v = ef4[ee * 8 + (c - 16)];
            }
            uint4 w;
            w.x = f2tf32(v.x); w.y = f2tf32(v.y); w.z = f2tf32(v.z); w.w = f2tf32(v.w);
            *(uint4*)(xin + e * XSTR + c * 4) = w;
        }
        __syncwarp();

        // ---- GEMM1: C1[16,64] = X[16,96] @ W1  (+b1 preloaded)
        float c1[8][4];
        #pragma unroll
        for (int nt = 0; nt < 8; nt++) {
            float2 bv = ((float2*)pb1)[nt * 4 + j];
            c1[nt][0] = bv.x; c1[nt][1] = bv.y;
            c1[nt][2] = bv.x; c1[nt][3] = bv.y;
        }
        #pragma unroll
        for (int kt = 0; kt < 12; kt++) {
            uint32_t a0 = *(uint32_t*)&xin[r0 * XSTR + kt * 8 + j];
            uint32_t a1 = *(uint32_t*)&xin[(r0 + 8) * XSTR + kt * 8 + j];
            uint32_t a2 = *(uint32_t*)&xin[r0 * XSTR + kt * 8 + j + 4];
            uint32_t a3 = *(uint32_t*)&xin[(r0 + 8) * XSTR + kt * 8 + j + 4];
            #pragma unroll
            for (int nt = 0; nt < 8; nt++) {
                float2 b = B1f[kt * 256 + nt * 32 + lane];
                mma16n8k8(c1[nt], a0, a1, a2, a3,
                          __float_as_uint(b.x), __float_as_uint(b.y));
            }
        }

        // ---- LayerNorm rows r0 and r0+8 (4-lane group reduction) + SiLU
        float s0 = 0.f, q0 = 0.f, s1 = 0.f, q1 = 0.f;
        #pragma unroll
        for (int nt = 0; nt < 8; nt++) {
            s0 += c1[nt][0] + c1[nt][1];
            q0 += c1[nt][0] * c1[nt][0] + c1[nt][1] * c1[nt][1];
            s1 += c1[nt][2] + c1[nt][3];
            q1 += c1[nt][2] * c1[nt][2] + c1[nt][3] * c1[nt][3];
        }
        #pragma unroll
        for (int off = 1; off <= 2; off <<= 1) {
            s0 += __shfl_xor_sync(FULL, s0, off);
            q0 += __shfl_xor_sync(FULL, q0, off);
            s1 += __shfl_xor_sync(FULL, s1, off);
            q1 += __shfl_xor_sync(FULL, q1, off);
        }
        float m0 = s0 * (1.0f / 64.0f), m1 = s1 * (1.0f / 64.0f);
        float rstd0 = rsqrtf(q0 * (1.0f / 64.0f) - m0 * m0 + 1e-5f);
        float rstd1 = rsqrtf(q1 * (1.0f / 64.0f) - m1 * m1 + 1e-5f);
        #pragma unroll
        for (int nt = 0; nt < 8; nt++) {
            float2 gv = ((float2*)pg)[nt * 4 + j];
            float2 bev = ((float2*)pbe)[nt * 4 + j];
            c1[nt][0] = silu_fast((c1[nt][0] - m0) * rstd0 * gv.x + bev.x);
            c1[nt][1] = silu_fast((c1[nt][1] - m0) * rstd0 * gv.y + bev.y);
            c1[nt][2] = silu_fast((c1[nt][2] - m1) * rstd1 * gv.x + bev.x);
            c1[nt][3] = silu_fast((c1[nt][3] - m1) * rstd1 * gv.y + bev.y);
        }
        // stage h (tf32) back into xin rows (cols 0..63)
        #pragma unroll
        for (int nt = 0; nt < 8; nt++) {
            uint2 u0, u1;
            u0.x = f2tf32(c1[nt][0]); u0.y = f2tf32(c1[nt][1]);
            u1.x = f2tf32(c1[nt][2]); u1.y = f2tf32(c1[nt][3]);
            *(uint2*)&xin[r0 * XSTR + nt * 8 + 2 * j] = u0;
            *(uint2*)&xin[(r0 + 8) * XSTR + nt * 8 + 2 * j] = u1;
        }
        __syncwarp();

        // ---- GEMM2: C2[16,64] = H[16,64] @ W2  (+b2 preloaded)
        float c2[8][4];
        #pragma unroll
        for (int nt = 0; nt < 8; nt++) {
            float2 bv = ((float2*)pb2)[nt * 4 + j];
            c2[nt][0] = bv.x; c2[nt][1] = bv.y;
            c2[nt][2] = bv.x; c2[nt][3] = bv.y;
        }
        #pragma unroll
        for (int kt = 0; kt < 8; kt++) {
            uint32_t a0 = *(uint32_t*)&xin[r0 * XSTR + kt * 8 + j];
            uint32_t a1 = *(uint32_t*)&xin[(r0 + 8) * XSTR + kt * 8 + j];
            uint32_t a2 = *(uint32_t*)&xin[r0 * XSTR + kt * 8 + j + 4];
            uint32_t a3 = *(uint32_t*)&xin[(r0 + 8) * XSTR + kt * 8 + j + 4];
            #pragma unroll
            for (int nt = 0; nt < 8; nt++) {
                float2 b = B2f[kt * 256 + nt * 32 + lane];
                mma16n8k8(c2[nt], a0, a1, a2, a3,
                          __float_as_uint(b.x), __float_as_uint(b.y));
            }
        }
        __syncwarp();   // xin h reads done before overwrite below

        // ---- SiLU + stage messages (f32) to xin
        #pragma unroll
        for (int nt = 0; nt < 8; nt++) {
            float2 v0, v1;
            v0.x = silu_fast(c2[nt][0]); v0.y = silu_fast(c2[nt][1]);
            v1.x = silu_fast(c2[nt][2]); v1.y = silu_fast(c2[nt][3]);
            *(float2*)&xin[r0 * XSTR + nt * 8 + 2 * j] = v0;
            *(float2*)&xin[(r0 + 8) * XSTR + nt * 8 + 2 * j] = v1;
        }
        __syncwarp();

        // ---- coalesced scatter: 2 lanes per edge row, 8x red.v4 each
        {
            int tg = __shfl_sync(FULL, tA, rr);
            if (e0 + rr < E) {
                float* basep = g_agg + (long long)tg * 64 + hf * 32;
                #pragma unroll
                for (int i = 0; i < 8; i++) {
                    float4 m = *(float4*)&xin[rr * XSTR + hf * 32 + i * 4];
                    asm volatile("red.global.add.v4.f32 [%0], {%1, %2, %3, %4};"
                                 :: "l"(basep + i * 4),
                                    "f"(m.x), "f"(m.y), "f"(m.z), "f"(m.w) : "memory");
                }
            }
        }
        __syncwarp();   // xin reused next tile
    }
}

// ---------------------------------------------------------------- node update (known-good scalar)
__global__ __launch_bounds__(256) void node_kernel(
    const float* __restrict__ nodef,
    const float* __restrict__ Wu, const float* __restrict__ bu,
    const float* __restrict__ gn, const float* __restrict__ bn,
    float* __restrict__ out, long long N)
{
    __shared__ float2 sWu[128 * 32];
    __shared__ float  sbu[64], sgn[64], sbn[64];

    for (int i = threadIdx.x; i < 128 * 32; i += blockDim.x) {
        int k = i >> 5, l = i & 31;
        sWu[i] = make_float2(Wu[k * 64 + 2 * l], Wu[k * 64 + 2 * l + 1]);
    }
    if (threadIdx.x < 64) {
        int t = threadIdx.x;
        sbu[t] = bu[t]; sgn[t] = gn[t]; sbn[t] = bn[t];
    }
    __syncthreads();

    const int lane = threadIdx.x & 31;
    const int warp = threadIdx.x >> 5;

    const float2 a0 = make_float2(sbu[2 * lane], sbu[2 * lane + 1]);
    const float gx = sgn[2 * lane], gy = sgn[2 * lane + 1];
    const float bx = sbn[2 * lane], by = sbn[2 * lane + 1];

    for (long long n = (long long)blockIdx.x * 8 + warp; n < N; n += (long long)gridDim.x * 8) {
        float ca = g_agg[n * 64 + lane];
        float cb = g_agg[n * 64 + 32 + lane];
        float cc = nodef[n * 64 + lane];
        float cd = nodef[n * 64 + 32 + lane];

        float2 a = a0;
        #pragma unroll
        for (int k = 0; k < 128; k++) {
            float x = (k < 32) ? __shfl_sync(FULL, ca, k)
                    : (k < 64) ? __shfl_sync(FULL, cb, k - 32)
                    : (k < 96) ? __shfl_sync(FULL, cc, k - 64)
                               : __shfl_sync(FULL, cd, k - 96);
            float2 w = sWu[k * 32 + lane];
            a.x = fmaf(x, w.x, a.x);
            a.y = fmaf(x, w.y, a.y);
        }
        a.x = silu_exact(a.x);
        a.y = silu_exact(a.y);

        float s = a.x + a.y;
        float q = a.x * a.x + a.y * a.y;
        #pragma unroll
        for (int off = 16; off; off >>= 1) {
            s += __shfl_xor_sync(FULL, s, off);
            q += __shfl_xor_sync(FULL, q, off);
        }
        float mean = s * (1.0f / 64.0f);
        float var  = q * (1.0f / 64.0f) - mean * mean;
        float rstd = rsqrtf(var + 1e-5f);
        float ox = (a.x - mean) * rstd * gx + bx;
        float oy = (a.y - mean) * rstd * gy + by;
        ((float2*)(out + n * 64))[lane] = make_float2(ox, oy);
    }
}

// ----------------------------------------------------------------
extern "C" void kernel_launch(void* const* d_in, const int* in_sizes, int n_in,
                              void* d_out, int out_size)
{
    const float* nodef = (const float*)d_in[0];
    const int*   ei    = (const int*)d_in[1];
    const float* edgef = (const float*)d_in[2];
    const float* W1    = (const float*)d_in[3];
    const float* b1    = (const float*)d_in[4];
    const float* g1    = (const float*)d_in[5];
    const float* be1   = (const float*)d_in[6];
    const float* W2    = (const float*)d_in[7];
    const float* b2    = (const float*)d_in[8];
    const float* Wu    = (const float*)d_in[9];
    const float* bu    = (const float*)d_in[10];
    const float* gn    = (const float*)d_in[11];
    const float* bn    = (const float*)d_in[12];

    long long N = (long long)in_sizes[0] / 64;
    long long E = (long long)in_sizes[1] / 2;
    float* out = (float*)d_out;

    // 1) zero the aggregation scratch
    long long n4 = N * 16;
    zero_kernel<<<(int)((n4 + 255) / 256), 256>>>(n4);

    // 2) edge MLP on tensor cores (mma.sync tf32) + scatter
    cudaFuncSetAttribute(edge_kernel, cudaFuncAttributeMaxDynamicSharedMemorySize, EDGE_SMEM);
    edge_kernel<<<296, 256, EDGE_SMEM>>>(nodef, ei, edgef, W1, b1, g1, be1, W2, b2, E);

    // 3) node update + final LayerNorm
    node_kernel<<<592, 256>>>(nodef, Wu, bu, gn, bn, out, N);
}

// round 8
// speedup vs baseline: 2.3883x; 1.2565x over previous
#include <cuda_runtime.h>
#include <cstdint>

// Inputs (metadata order):
// 0 node_features (N,64) f32
// 1 edge_index    (2,E)  int32
// 2 edge_features (E,32) f32
// 3 W1 (96,64)  4 b1(64)  5 g1(64)  6 be1(64)
// 7 W2 (64,64)  8 b2(64)
// 9 Wu (128,64) 10 bu(64) 11 gn(64) 12 bn(64)
// out: (N,64) f32

#define FULL 0xFFFFFFFFu
#define MAX_N 80000

__device__ __align__(16) float g_agg[(size_t)MAX_N * 64];

__device__ __forceinline__ float silu_exact(float v) {
    return v * (1.0f / (1.0f + __expf(-v)));
}
// fast silu: v * 0.5*(1+tanh(v/2)) — 1 MUFU
__device__ __forceinline__ float silu_fast(float v) {
    float t;
    asm("tanh.approx.f32 %0, %1;" : "=f"(t) : "f"(v * 0.5f));
    float hv = 0.5f * v;
    return fmaf(hv, t, hv);
}
__device__ __forceinline__ uint32_t f2tf32(float f) {
    uint32_t r;
    asm("cvt.rna.tf32.f32 %0, %1;" : "=r"(r) : "f"(f));
    return r;
}
__device__ __forceinline__ uint32_t smem_u32(const void* p) {
    uint32_t a;
    asm("{ .reg .u64 t; cvta.to.shared.u64 t, %1; cvt.u32.u64 %0, t; }" : "=r"(a) : "l"(p));
    return a;
}
__device__ __forceinline__ void cp_async16(uint32_t dst, const void* src) {
    asm volatile("cp.async.ca.shared.global [%0], [%1], 16;" :: "r"(dst), "l"(src) : "memory");
}
#define CP_COMMIT() asm volatile("cp.async.commit_group;" ::: "memory")
#define CP_WAIT0()  asm volatile("cp.async.wait_group 0;" ::: "memory")

__device__ __forceinline__ void mma16n8k8(float c[4], uint32_t a0, uint32_t a1,
                                          uint32_t a2, uint32_t a3,
                                          uint32_t b0, uint32_t b1) {
    asm volatile(
        "mma.sync.aligned.m16n8k8.row.col.f32.tf32.tf32.f32 "
        "{%0,%1,%2,%3}, {%4,%5,%6,%7}, {%8,%9}, {%0,%1,%2,%3};"
        : "+f"(c[0]), "+f"(c[1]), "+f"(c[2]), "+f"(c[3])
        : "r"(a0), "r"(a1), "r"(a2), "r"(a3), "r"(b0), "r"(b1));
}

// ---------------------------------------------------------------- zero agg
__global__ void zero_kernel(long long n4) {
    long long i = (long long)blockIdx.x * blockDim.x + threadIdx.x;
    if (i < n4) ((float4*)g_agg)[i] = make_float4(0.f, 0.f, 0.f, 0.f);
}

// ---------------------------------------------------------------- edge MLP (mma.sync tf32, pipelined) + scatter
// dynamic smem (floats): B1f 12*8*32 f2 | B2f 8*8*32 f2 | pb1,pg,pbe,pb2 4*64 | xin 8*16*100
#define XSTR 100
#define EDGE_SMEM 93184

__global__ __launch_bounds__(256, 2) void edge_kernel(
    const float* __restrict__ nodef,
    const int* __restrict__ ei,
    const float* __restrict__ edgef,
    const float* __restrict__ W1, const float* __restrict__ b1,
    const float* __restrict__ g1, const float* __restrict__ be1,
    const float* __restrict__ W2, const float* __restrict__ b2,
    long long E)
{
    extern __shared__ __align__(16) float smem[];
    float2* B1f = (float2*)smem;            // [12*8*32]
    float2* B2f = B1f + 12 * 8 * 32;        // [8*8*32]
    float*  pb1 = (float*)(B2f + 8 * 8 * 32);
    float*  pg  = pb1 + 64;
    float*  pbe = pg + 64;
    float*  pb2 = pbe + 64;
    float*  xall = pb2 + 64;

    const int t = threadIdx.x;
    const int warp = t >> 5;
    const int lane = t & 31;

    // pack W1^T, W2^T into B-fragment order (tf32-converted)
    for (int i = t; i < 12 * 8 * 32; i += 256) {
        int kt = i >> 8, nt = (i >> 5) & 7, l = i & 31;
        int k = kt * 8 + (l & 3), n = nt * 8 + (l >> 2);
        float2 v;
        v.x = __uint_as_float(f2tf32(W1[k * 64 + n]));
        v.y = __uint_as_float(f2tf32(W1[(k + 4) * 64 + n]));
        B1f[i] = v;
    }
    for (int i = t; i < 8 * 8 * 32; i += 256) {
        int kt = i >> 8, nt = (i >> 5) & 7, l = i & 31;
        int k = kt * 8 + (l & 3), n = nt * 8 + (l >> 2);
        float2 v;
        v.x = __uint_as_float(f2tf32(W2[k * 64 + n]));
        v.y = __uint_as_float(f2tf32(W2[(k + 4) * 64 + n]));
        B2f[i] = v;
    }
    if (t < 64) { pb1[t] = b1[t]; pg[t] = g1[t]; pbe[t] = be1[t]; pb2[t] = b2[t]; }
    __syncthreads();

    float* xin = xall + warp * (16 * XSTR);
    const uint32_t xin_u = smem_u32(xin);
    const int j = lane & 3;
    const int r0 = lane >> 2;
    const int grp = lane & ~3;
    const int s0l = grp + (j >> 1);        // shuffle src for GEMM2 a0/a1
    const int s2l = grp + 2 + (j >> 1);    // shuffle src for GEMM2 a2/a3

    const float4* nf4 = (const float4*)nodef;
    const float4* ef4 = (const float4*)edgef;
    const int* srcp = ei;
    const int* tgtp = ei + E;

    const long long G = (E + 15) >> 4;
    const long long wstride = (long long)gridDim.x * 8;

    long long g = (long long)blockIdx.x * 8 + warp;
    if (g >= G) return;

    // ---- prologue: prefetch tile g indices + issue its gather
    int sA = 0, tA = 0;
    if (lane < 16) {
        long long ee = (g << 4) + lane; if (ee >= E) ee = E - 1;
        sA = srcp[ee]; tA = tgtp[ee];
    }
    {
        const long long e0 = g << 4;
        #pragma unroll
        for (int i = 0; i < 12; i++) {
            int idx = lane + 32 * i;
            int e = idx / 24, c = idx - e * 24;
            const float4* src;
            if (c < 16) {
                int s = __shfl_sync(FULL, sA, e);
                src = nf4 + (long long)s * 16 + c;
            } else {
                long long ee = e0 + e; if (ee >= E) ee = E - 1;
                src = ef4 + ee * 8 + (c - 16);
            }
            cp_async16(xin_u + (uint32_t)(e * XSTR + c * 4) * 4, src);
        }
        CP_COMMIT();
    }

    for (; g < G; g += wstride) {
        const long long e0 = g << 4;
        const long long gn = g + wstride;

        CP_WAIT0();
        __syncwarp();

        // ---- GEMM1: C1[16,64] = X[16,96] @ W1  (+b1 preloaded); A-frags from xin
        float c1[8][4];
        #pragma unroll
        for (int nt = 0; nt < 8; nt++) {
            float2 bv = ((float2*)pb1)[nt * 4 + j];
            c1[nt][0] = bv.x; c1[nt][1] = bv.y;
            c1[nt][2] = bv.x; c1[nt][3] = bv.y;
        }
        #pragma unroll
        for (int kt = 0; kt < 12; kt++) {
            uint32_t a0 = *(uint32_t*)&xin[r0 * XSTR + kt * 8 + j];
            uint32_t a1 = *(uint32_t*)&xin[(r0 + 8) * XSTR + kt * 8 + j];
            uint32_t a2 = *(uint32_t*)&xin[r0 * XSTR + kt * 8 + j + 4];
            uint32_t a3 = *(uint32_t*)&xin[(r0 + 8) * XSTR + kt * 8 + j + 4];
            #pragma unroll
            for (int nt = 0; nt < 8; nt++) {
                float2 b = B1f[kt * 256 + nt * 32 + lane];
                mma16n8k8(c1[nt], a0, a1, a2, a3,
                          __float_as_uint(b.x), __float_as_uint(b.y));
            }
        }
        __syncwarp();   // all lanes done reading xin

        // ---- prefetch next tile: indices + cp.async gather into xin
        int sA2 = 0, tA2 = 0;
        if (lane < 16) {
            long long ee = (gn << 4) + lane; if (ee >= E) ee = E - 1;
            sA2 = srcp[ee]; tA2 = tgtp[ee];
        }
        {
            const long long e0n = gn << 4;
            #pragma unroll
            for (int i = 0; i < 12; i++) {
                int idx = lane + 32 * i;
                int e = idx / 24, c = idx - e * 24;
                const float4* src;
                if (c < 16) {
                    int s = __shfl_sync(FULL, sA2, e);
                    src = nf4 + (long long)s * 16 + c;
                } else {
                    long long ee = e0n + e; if (ee >= E) ee = E - 1;
                    src = ef4 + ee * 8 + (c - 16);
                }
                cp_async16(xin_u + (uint32_t)(e * XSTR + c * 4) * 4, src);
            }
            CP_COMMIT();
        }

        // ---- LayerNorm rows r0, r0+8 (4-lane group reduce) + SiLU -> tf32 bits
        float s0 = 0.f, q0 = 0.f, s1 = 0.f, q1 = 0.f;
        #pragma unroll
        for (int nt = 0; nt < 8; nt++) {
            s0 += c1[nt][0] + c1[nt][1];
            q0 += c1[nt][0] * c1[nt][0] + c1[nt][1] * c1[nt][1];
            s1 += c1[nt][2] + c1[nt][3];
            q1 += c1[nt][2] * c1[nt][2] + c1[nt][3] * c1[nt][3];
        }
        #pragma unroll
        for (int off = 1; off <= 2; off <<= 1) {
            s0 += __shfl_xor_sync(FULL, s0, off);
            q0 += __shfl_xor_sync(FULL, q0, off);
            s1 += __shfl_xor_sync(FULL, s1, off);
            q1 += __shfl_xor_sync(FULL, q1, off);
        }
        float m0 = s0 * (1.0f / 64.0f), m1 = s1 * (1.0f / 64.0f);
        float rstd0 = rsqrtf(q0 * (1.0f / 64.0f) - m0 * m0 + 1e-5f);
        float rstd1 = rsqrtf(q1 * (1.0f / 64.0f) - m1 * m1 + 1e-5f);
        uint32_t hc[8][4];
        #pragma unroll
        for (int nt = 0; nt < 8; nt++) {
            float2 gv = ((float2*)pg)[nt * 4 + j];
            float2 bev = ((float2*)pbe)[nt * 4 + j];
            hc[nt][0] = f2tf32(silu_fast((c1[nt][0] - m0) * rstd0 * gv.x + bev.x));
            hc[nt][1] = f2tf32(silu_fast((c1[nt][1] - m0) * rstd0 * gv.y + bev.y));
            hc[nt][2] = f2tf32(silu_fast((c1[nt][2] - m1) * rstd1 * gv.x + bev.x));
            hc[nt][3] = f2tf32(silu_fast((c1[nt][3] - m1) * rstd1 * gv.y + bev.y));
        }

        // ---- GEMM2: C2[16,64] = H[16,64] @ W2; A-frags via intra-group shuffles of hc
        float c2[8][4];
        #pragma unroll
        for (int nt = 0; nt < 8; nt++) {
            float2 bv = ((float2*)pb2)[nt * 4 + j];
            c2[nt][0] = bv.x; c2[nt][1] = bv.y;
            c2[nt][2] = bv.x; c2[nt][3] = bv.y;
        }
        #pragma unroll
        for (int kt = 0; kt < 8; kt++) {
            uint32_t v00 = __shfl_sync(FULL, hc[kt][0], s0l);
            uint32_t v01 = __shfl_sync(FULL, hc[kt][1], s0l);
            uint32_t v10 = __shfl_sync(FULL, hc[kt][2], s0l);
            uint32_t v11 = __shfl_sync(FULL, hc[kt][3], s0l);
            uint32_t v20 = __shfl_sync(FULL, hc[kt][0], s2l);
            uint32_t v21 = __shfl_sync(FULL, hc[kt][1], s2l);
            uint32_t v30 = __shfl_sync(FULL, hc[kt][2], s2l);
            uint32_t v31 = __shfl_sync(FULL, hc[kt][3], s2l);
            uint32_t a0 = (j & 1) ? v01 : v00;
            uint32_t a1 = (j & 1) ? v11 : v10;
            uint32_t a2 = (j & 1) ? v21 : v20;
            uint32_t a3 = (j & 1) ? v31 : v30;
            #pragma unroll
            for (int nt = 0; nt < 8; nt++) {
                float2 b = B2f[kt * 256 + nt * 32 + lane];
                mma16n8k8(c2[nt], a0, a1, a2, a3,
                          __float_as_uint(b.x), __float_as_uint(b.y));
            }
        }

        // ---- SiLU + direct register scatter: red.v2 per (row, nt) pair
        {
            int tg0 = __shfl_sync(FULL, tA, r0);
            int tg1 = __shfl_sync(FULL, tA, r0 + 8);
            bool ok0 = (e0 + r0 < E);
            bool ok1 = (e0 + r0 + 8 < E);
            float* p0 = g_agg + (long long)tg0 * 64 + 2 * j;
            float* p1 = g_agg + (long long)tg1 * 64 + 2 * j;
            #pragma unroll
            for (int nt = 0; nt < 8; nt++) {
                float mx0 = silu_fast(c2[nt][0]);
                float my0 = silu_fast(c2[nt][1]);
                float mx1 = silu_fast(c2[nt][2]);
                float my1 = silu_fast(c2[nt][3]);
                if (ok0)
                    asm volatile("red.global.add.v2.f32 [%0], {%1, %2};"
                                 :: "l"(p0 + nt * 8), "f"(mx0), "f"(my0) : "memory");
                if (ok1)
                    asm volatile("red.global.add.v2.f32 [%0], {%1, %2};"
                                 :: "l"(p1 + nt * 8), "f"(mx1), "f"(my1) : "memory");
            }
        }

        sA = sA2; tA = tA2;
    }
}

// ---------------------------------------------------------------- node update (known-good)
__global__ __launch_bounds__(256) void node_kernel(
    const float* __restrict__ nodef,
    const float* __restrict__ Wu, const float* __restrict__ bu,
    const float* __restrict__ gn, const float* __restrict__ bn,
    float* __restrict__ out, long long N)
{
    __shared__ float2 sWu[128 * 32];
    __shared__ float  sbu[64], sgn[64], sbn[64];

    for (int i = threadIdx.x; i < 128 * 32; i += blockDim.x) {
        int k = i >> 5, l = i & 31;
        sWu[i] = make_float2(Wu[k * 64 + 2 * l], Wu[k * 64 + 2 * l + 1]);
    }
    if (threadIdx.x < 64) {
        int t = threadIdx.x;
        sbu[t] = bu[t]; sgn[t] = gn[t]; sbn[t] = bn[t];
    }
    __syncthreads();

    const int lane = threadIdx.x & 31;
    const int warp = threadIdx.x >> 5;

    const float2 a0 = make_float2(sbu[2 * lane], sbu[2 * lane + 1]);
    const float gx = sgn[2 * lane], gy = sgn[2 * lane + 1];
    const float bx = sbn[2 * lane], by = sbn[2 * lane + 1];

    for (long long n = (long long)blockIdx.x * 8 + warp; n < N; n += (long long)gridDim.x * 8) {
        float ca = g_agg[n * 64 + lane];
        float cb = g_agg[n * 64 + 32 + lane];
        float cc = nodef[n * 64 + lane];
        float cd = nodef[n * 64 + 32 + lane];

        float2 a = a0;
        #pragma unroll
        for (int k = 0; k < 128; k++) {
            float x = (k < 32) ? __shfl_sync(FULL, ca, k)
                    : (k < 64) ? __shfl_sync(FULL, cb, k - 32)
                    : (k < 96) ? __shfl_sync(FULL, cc, k - 64)
                               : __shfl_sync(FULL, cd, k - 96);
            float2 w = sWu[k * 32 + lane];
            a.x = fmaf(x, w.x, a.x);
            a.y = fmaf(x, w.y, a.y);
        }
        a.x = silu_exact(a.x);
        a.y = silu_exact(a.y);

        float s = a.x + a.y;
        float q = a.x * a.x + a.y * a.y;
        #pragma unroll
        for (int off = 16; off; off >>= 1) {
            s += __shfl_xor_sync(FULL, s, off);
            q += __shfl_xor_sync(FULL, q, off);
        }
        float mean = s * (1.0f / 64.0f);
        float var  = q * (1.0f / 64.0f) - mean * mean;
        float rstd = rsqrtf(var + 1e-5f);
        float ox = (a.x - mean) * rstd * gx + bx;
        float oy = (a.y - mean) * rstd * gy + by;
        ((float2*)(out + n * 64))[lane] = make_float2(ox, oy);
    }
}

// ----------------------------------------------------------------
extern "C" void kernel_launch(void* const* d_in, const int* in_sizes, int n_in,
                              void* d_out, int out_size)
{
    const float* nodef = (const float*)d_in[0];
    const int*   ei    = (const int*)d_in[1];
    const float* edgef = (const float*)d_in[2];
    const float* W1    = (const float*)d_in[3];
    const float* b1    = (const float*)d_in[4];
    const float* g1    = (const float*)d_in[5];
    const float* be1   = (const float*)d_in[6];
    const float* W2    = (const float*)d_in[7];
    const float* b2    = (const float*)d_in[8];
    const float* Wu    = (const float*)d_in[9];
    const float* bu    = (const float*)d_in[10];
    const float* gn    = (const float*)d_in[11];
    const float* bn    = (const float*)d_in[12];

    long long N = (long long)in_sizes[0] / 64;
    long long E = (long long)in_sizes[1] / 2;
    float* out = (float*)d_out;

    // 1) zero the aggregation scratch
    long long n4 = N * 16;
    zero_kernel<<<(int)((n4 + 255) / 256), 256>>>(n4);

    // 2) edge MLP on tensor cores (pipelined cp.async gather) + scatter
    cudaFuncSetAttribute(edge_kernel, cudaFuncAttributeMaxDynamicSharedMemorySize, EDGE_SMEM);
    edge_kernel<<<296, 256, EDGE_SMEM>>>(nodef, ei, edgef, W1, b1, g1, be1, W2, b2, E);

    // 3) node update + final LayerNorm
    node_kernel<<<592, 256>>>(nodef, Wu, bu, gn, bn, out, N);
}